// round 1
// baseline (speedup 1.0000x reference)
#include <cuda_runtime.h>
#include <math.h>

// Problem constants
#define Bn      2048
#define Ln      128
#define Cn      150
#define Hn      230
#define HT      64          // h per block
#define NBH     4           // ceil(230/64)
#define THREADS 256
#define LT      32          // l per thread (4 quarters * 32 = 128)

#define NCC2      225       // 75 channel-pairs * 3 taps
#define WS_STRIDE 65        // float2 stride per cc2 row (odd -> fewer bank conflicts)
#define XS_STRIDE 152       // floats per padded x row (150 rounded to mult of 4, even)
#define XROWS     130       // 128 + 2 zero-pad rows

#define SMEM_FLOATS (NCC2*WS_STRIDE*2 + XROWS*XS_STRIDE + 128 + THREADS*3)
#define SMEM_BYTES  (SMEM_FLOATS * 4)

__device__ __forceinline__ void ffma2(unsigned long long &d,
                                      unsigned long long a,
                                      unsigned long long b) {
    // packed f32x2 fused multiply-add (sm_100+): d.lo/hi += a.lo/hi * b.lo/hi
    asm("fma.rn.f32x2 %0, %1, %2, %0;" : "+l"(d) : "l"(a), "l"(b));
}

__global__ __launch_bounds__(THREADS, 1)
void pcnn_conv_pool_kernel(const float* __restrict__ Xea,
                           const int*   __restrict__ Xmask,
                           const float* __restrict__ W,
                           const float* __restrict__ bias,
                           float*       __restrict__ out)
{
    extern __shared__ float smem[];
    float2* Ws2 = reinterpret_cast<float2*>(smem);              // [225][65] float2
    float*  Xs  = smem + NCC2 * WS_STRIDE * 2;                  // [130][152] floats
    int*    ms  = reinterpret_cast<int*>(Xs + XROWS * XS_STRIDE); // [128] ints
    float*  red = reinterpret_cast<float*>(ms + Ln);            // [4][64][3] floats

    const int t  = threadIdx.x;
    const int b  = blockIdx.x;
    const int h0 = blockIdx.y * HT;
    const int ht = t & (HT - 1);
    const int q  = t >> 6;        // which 32-row quarter of L
    const int h  = h0 + ht;

    // ---- stage Xea[b] into shared with zero-pad rows 0 and 129 ----
    const float* xg = Xea + (size_t)b * (Ln * Cn);
    for (int idx = t; idx < Ln * Cn; idx += THREADS) {
        int row = idx / Cn;
        int col = idx - row * Cn;
        Xs[(row + 1) * XS_STRIDE + col] = xg[idx];
    }
    for (int idx = t; idx < 2 * XS_STRIDE; idx += THREADS) {
        if (idx < XS_STRIDE) Xs[idx] = 0.0f;
        else                 Xs[(XROWS - 1) * XS_STRIDE + (idx - XS_STRIDE)] = 0.0f;
    }

    // ---- stage W transposed & channel-paired:
    // Ws2[cc2][hh] = { W[h0+hh][2*c2][k], W[h0+hh][2*c2+1][k] },  cc2 = c2*3 + k ----
    for (int idx = t; idx < NCC2 * HT; idx += THREADS) {
        int cc2 = idx % NCC2;     // lanes sweep cc2 -> semi-coalesced global reads
        int hh  = idx / NCC2;
        int hg  = h0 + hh;
        int c2  = cc2 / 3;
        int k   = cc2 - 3 * c2;
        float wa = 0.0f, wb = 0.0f;
        if (hg < Hn) {
            const float* wp = W + (size_t)hg * (Cn * 3) + c2 * 6 + k;
            wa = wp[0];   // channel 2*c2,   tap k
            wb = wp[3];   // channel 2*c2+1, tap k
        }
        Ws2[cc2 * WS_STRIDE + hh] = make_float2(wa, wb);
    }

    if (t < Ln) ms[t] = Xmask[b * Ln + t];
    __syncthreads();

    // ---- conv: acc2[i] packs {even-channel partial, odd-channel partial} for output l0+i ----
    unsigned long long acc[LT];
#pragma unroll
    for (int i = 0; i < LT; ++i) acc[i] = 0ull;

    const int l0 = q * LT;
    for (int c2 = 0; c2 < Cn / 2; ++c2) {
        unsigned long long w0 = *reinterpret_cast<const unsigned long long*>(
            &Ws2[(c2 * 3 + 0) * WS_STRIDE + ht]);
        unsigned long long w1 = *reinterpret_cast<const unsigned long long*>(
            &Ws2[(c2 * 3 + 1) * WS_STRIDE + ht]);
        unsigned long long w2 = *reinterpret_cast<const unsigned long long*>(
            &Ws2[(c2 * 3 + 2) * WS_STRIDE + ht]);

        const float* xcol = Xs + l0 * XS_STRIDE + 2 * c2;
#pragma unroll
        for (int j = 0; j <= LT + 1; ++j) {
            // xpad row l0+j: contributes to outputs l0+j (tap0), l0+j-1 (tap1), l0+j-2 (tap2)
            unsigned long long xv = *reinterpret_cast<const unsigned long long*>(
                xcol + j * XS_STRIDE);          // broadcast across warp (same l0, c2)
            if (j <= LT - 1)           ffma2(acc[j],     xv, w0);
            if (j >= 1 && j <= LT)     ffma2(acc[j - 1], xv, w1);
            if (j >= 2)                ffma2(acc[j - 2], xv, w2);
        }
    }

    // ---- masked piecewise max over this thread's 32 rows ----
    const float bh = (h < Hn) ? bias[h] : 0.0f;
    float pm0 = 0.0f, pm1 = 0.0f, pm2 = 0.0f;   // zero floor matches reference (m=0 rows)
#pragma unroll
    for (int i = 0; i < LT; ++i) {
        float y = __uint_as_float((unsigned)acc[i]) +
                  __uint_as_float((unsigned)(acc[i] >> 32)) + bh;
        int mk = ms[l0 + i];
        if      (mk == 1) pm0 = fmaxf(pm0, y);
        else if (mk == 2) pm1 = fmaxf(pm1, y);
        else if (mk == 3) pm2 = fmaxf(pm2, y);
    }
    red[(q * HT + ht) * 3 + 0] = pm0;
    red[(q * HT + ht) * 3 + 1] = pm1;
    red[(q * HT + ht) * 3 + 2] = pm2;
    __syncthreads();

    // ---- combine 4 quarters, tanh, write [B, H*3] ----
    if (t < HT && h < Hn) {
#pragma unroll
        for (int j = 0; j < 3; ++j) {
            float m = red[(0 * HT + t) * 3 + j];
            m = fmaxf(m, red[(1 * HT + t) * 3 + j]);
            m = fmaxf(m, red[(2 * HT + t) * 3 + j]);
            m = fmaxf(m, red[(3 * HT + t) * 3 + j]);
            out[(size_t)b * (3 * Hn) + h * 3 + j] = tanhf(m);
        }
    }
}

extern "C" void kernel_launch(void* const* d_in, const int* in_sizes, int n_in,
                              void* d_out, int out_size)
{
    const float* Xea   = (const float*)d_in[0];
    const int*   Xmask = (const int*)  d_in[1];
    const float* W     = (const float*)d_in[2];
    const float* bias  = (const float*)d_in[3];
    float*       out   = (float*)d_out;

    cudaFuncSetAttribute(pcnn_conv_pool_kernel,
                         cudaFuncAttributeMaxDynamicSharedMemorySize, SMEM_BYTES);

    dim3 grid(Bn, NBH);
    pcnn_conv_pool_kernel<<<grid, THREADS, SMEM_BYTES>>>(Xea, Xmask, W, bias, out);
}

// round 2
// speedup vs baseline: 1.2424x; 1.2424x over previous
#include <cuda_runtime.h>
#include <math.h>

// Problem constants
#define Bn      2048
#define Ln      128
#define Cn      150
#define Hn      230
#define HT      64          // h per block
#define NBH     4           // ceil(230/64)
#define THREADS 512
#define NQ      8           // L-quarters per block
#define LT      16          // l rows per thread (8 quarters * 16 = 128)

#define NCC2      225       // 75 channel-pairs * 3 taps
#define WS_STRIDE 65        // float2 stride per cc2 row (odd -> fewer bank conflicts)
#define XS_STRIDE 152       // floats per padded x row
#define XROWS     130       // 128 + 2 zero-pad rows

#define SMEM_FLOATS (NCC2*WS_STRIDE*2 + XROWS*XS_STRIDE + 128 + NQ*HT*3)
#define SMEM_BYTES  (SMEM_FLOATS * 4)

__device__ __forceinline__ void ffma2(unsigned long long &d,
                                      unsigned long long a,
                                      unsigned long long b) {
    // packed f32x2 fused multiply-add (sm_100+): d.lo/hi += a.lo/hi * b.lo/hi
    asm("fma.rn.f32x2 %0, %1, %2, %0;" : "+l"(d) : "l"(a), "l"(b));
}

__global__ __launch_bounds__(THREADS, 1)
void pcnn_conv_pool_kernel(const float* __restrict__ Xea,
                           const int*   __restrict__ Xmask,
                           const float* __restrict__ W,
                           const float* __restrict__ bias,
                           float*       __restrict__ out)
{
    extern __shared__ float smem[];
    float2* Ws2 = reinterpret_cast<float2*>(smem);                // [225][65] float2
    float*  Xs  = smem + NCC2 * WS_STRIDE * 2;                    // [130][152] floats
    int*    ms  = reinterpret_cast<int*>(Xs + XROWS * XS_STRIDE); // [128] ints
    float*  red = reinterpret_cast<float*>(ms + Ln);              // [8][64][3] floats

    const int t  = threadIdx.x;
    const int b  = blockIdx.x;
    const int h0 = blockIdx.y * HT;
    const int ht = t & (HT - 1);
    const int q  = t >> 6;        // which 16-row quarter of L (0..7)
    const int h  = h0 + ht;

    // ---- stage Xea[b] into shared with zero-pad rows 0 and 129 ----
    const float* xg = Xea + (size_t)b * (Ln * Cn);
    for (int idx = t; idx < Ln * Cn; idx += THREADS) {
        int row = idx / Cn;
        int col = idx - row * Cn;
        Xs[(row + 1) * XS_STRIDE + col] = xg[idx];
    }
    for (int idx = t; idx < 2 * XS_STRIDE; idx += THREADS) {
        if (idx < XS_STRIDE) Xs[idx] = 0.0f;
        else                 Xs[(XROWS - 1) * XS_STRIDE + (idx - XS_STRIDE)] = 0.0f;
    }

    // ---- stage W transposed & channel-paired:
    // Ws2[cc2][hh] = { W[h0+hh][2*c2][k], W[h0+hh][2*c2+1][k] },  cc2 = c2*3 + k ----
    for (int idx = t; idx < NCC2 * HT; idx += THREADS) {
        int cc2 = idx % NCC2;     // lanes sweep cc2 -> semi-coalesced global reads
        int hh  = idx / NCC2;
        int hg  = h0 + hh;
        int c2  = cc2 / 3;
        int k   = cc2 - 3 * c2;
        float wa = 0.0f, wb = 0.0f;
        if (hg < Hn) {
            const float* wp = W + (size_t)hg * (Cn * 3) + c2 * 6 + k;
            wa = wp[0];   // channel 2*c2,   tap k
            wb = wp[3];   // channel 2*c2+1, tap k
        }
        Ws2[cc2 * WS_STRIDE + hh] = make_float2(wa, wb);
    }

    if (t < Ln) ms[t] = Xmask[b * Ln + t];
    __syncthreads();

    // ---- conv: acc[i] packs {even-channel partial, odd-channel partial} for output l0+i ----
    unsigned long long acc[LT];
#pragma unroll
    for (int i = 0; i < LT; ++i) acc[i] = 0ull;

    const int l0 = q * LT;
    for (int c2 = 0; c2 < Cn / 2; ++c2) {
        unsigned long long w0 = *reinterpret_cast<const unsigned long long*>(
            &Ws2[(c2 * 3 + 0) * WS_STRIDE + ht]);
        unsigned long long w1 = *reinterpret_cast<const unsigned long long*>(
            &Ws2[(c2 * 3 + 1) * WS_STRIDE + ht]);
        unsigned long long w2 = *reinterpret_cast<const unsigned long long*>(
            &Ws2[(c2 * 3 + 2) * WS_STRIDE + ht]);

        const float* xcol = Xs + l0 * XS_STRIDE + 2 * c2;
#pragma unroll
        for (int j = 0; j <= LT + 1; ++j) {
            // xpad row l0+j: contributes to outputs l0+j (tap0), l0+j-1 (tap1), l0+j-2 (tap2)
            unsigned long long xv = *reinterpret_cast<const unsigned long long*>(
                xcol + j * XS_STRIDE);          // broadcast across warp (same l0, c2)
            if (j <= LT - 1)           ffma2(acc[j],     xv, w0);
            if (j >= 1 && j <= LT)     ffma2(acc[j - 1], xv, w1);
            if (j >= 2)                ffma2(acc[j - 2], xv, w2);
        }
    }

    // ---- masked piecewise max over this thread's 16 rows ----
    const float bh = (h < Hn) ? bias[h] : 0.0f;
    float pm0 = 0.0f, pm1 = 0.0f, pm2 = 0.0f;   // zero floor matches reference (m=0 rows)
#pragma unroll
    for (int i = 0; i < LT; ++i) {
        float y = __uint_as_float((unsigned)acc[i]) +
                  __uint_as_float((unsigned)(acc[i] >> 32)) + bh;
        int mk = ms[l0 + i];
        if      (mk == 1) pm0 = fmaxf(pm0, y);
        else if (mk == 2) pm1 = fmaxf(pm1, y);
        else if (mk == 3) pm2 = fmaxf(pm2, y);
    }
    red[(q * HT + ht) * 3 + 0] = pm0;
    red[(q * HT + ht) * 3 + 1] = pm1;
    red[(q * HT + ht) * 3 + 2] = pm2;
    __syncthreads();

    // ---- combine 8 quarters, tanh, write [B, H*3] ----
    if (t < HT && h < Hn) {
#pragma unroll
        for (int j = 0; j < 3; ++j) {
            float m = red[(0 * HT + t) * 3 + j];
#pragma unroll
            for (int qq = 1; qq < NQ; ++qq)
                m = fmaxf(m, red[(qq * HT + t) * 3 + j]);
            out[(size_t)b * (3 * Hn) + h * 3 + j] = tanhf(m);
        }
    }
}

extern "C" void kernel_launch(void* const* d_in, const int* in_sizes, int n_in,
                              void* d_out, int out_size)
{
    const float* Xea   = (const float*)d_in[0];
    const int*   Xmask = (const int*)  d_in[1];
    const float* W     = (const float*)d_in[2];
    const float* bias  = (const float*)d_in[3];
    float*       out   = (float*)d_out;

    cudaFuncSetAttribute(pcnn_conv_pool_kernel,
                         cudaFuncAttributeMaxDynamicSharedMemorySize, SMEM_BYTES);

    dim3 grid(Bn, NBH);
    pcnn_conv_pool_kernel<<<grid, THREADS, SMEM_BYTES>>>(Xea, Xmask, W, bias, out);
}

// round 4
// speedup vs baseline: 4.4499x; 3.5817x over previous
#include <cuda_runtime.h>
#include <cuda_fp16.h>
#include <cstdint>
#include <math.h>

#define Bn 2048
#define Ln 128
#define Cn 150
#define Hn 230

// X tile geometry (fp16, hi/lo split), row stride 168 halves = 336B (conflict-free ldmatrix)
#define XRS   168
#define XROWB 336
#define XSPLT (130*XROWB)        // 43,680 B per split per batch
#define XBAT  (2*XSPLT)          // 87,360 B per batch
#define XUNIT (66*XROWB)         // 22,176 B per (split, m-half) unit copy
#define XBUFB (2*XUNIT)          // 44,352 B per X smem buffer

// W geometry: [hh][128 n][488 k] fp16, k = tap*160 + c
#define WRS   488
#define WROWB 976
#define WTILE (128*WROWB)        // 124,928 B per h-half

// smem layout
#define MB_W  0
#define MB_X0 8
#define MB_X1 16
#define SM_MS 32                 // int ms[128]
#define SM_W  1024
#define SM_X0 126976             // SM_W + 124928 -> 125952, round to 1024
#define SM_X1 (SM_X0 + XBUFB)   // 171,328
#define SMEM_BYTES (SM_X1 + XBUFB)  // 215,680

__device__ __align__(128) __half Xg[(size_t)Bn * 2 * 130 * XRS];  // ~179MB
__device__ __align__(128) __half Wg[2 * 128 * WRS];

// ---------------- prepass: X -> fp16 hi/lo padded tiles ----------------
__global__ void xprep(const float* __restrict__ Xea) {
    int idx = blockIdx.x * blockDim.x + threadIdx.x;   // Bn*130*21
    if (idx >= Bn * 130 * 21) return;
    int g   = idx % 21;
    int row = (idx / 21) % 130;
    int b   = idx / (21 * 130);
    __align__(16) __half h8[8];
    __align__(16) __half l8[8];
    if (row == 0 || row == 129) {
#pragma unroll
        for (int i = 0; i < 8; ++i) { h8[i] = __float2half(0.f); l8[i] = h8[i]; }
    } else {
        const float* src = Xea + ((size_t)b * Ln + (row - 1)) * Cn;
#pragma unroll
        for (int i = 0; i < 8; ++i) {
            int c = g * 8 + i;
            float v = (c < Cn) ? src[c] : 0.f;
            __half hi = __float2half(v);
            h8[i] = hi;
            l8[i] = __float2half(v - __half2float(hi));
        }
    }
    size_t o0 = ((size_t)(b * 2 + 0) * 130 + row) * XRS + g * 8;
    size_t o1 = ((size_t)(b * 2 + 1) * 130 + row) * XRS + g * 8;
    *(uint4*)(&Xg[o0]) = *(uint4*)h8;
    *(uint4*)(&Xg[o1]) = *(uint4*)l8;
}

// ---------------- prepass: W -> fp16 [hh][n][k] ----------------
__global__ void wprep(const float* __restrict__ W) {
    int idx = blockIdx.x * blockDim.x + threadIdx.x;   // 2*128*488
    if (idx >= 2 * 128 * WRS) return;
    int k  = idx % WRS;
    int n  = (idx / WRS) % 128;
    int hh = idx / (WRS * 128);
    int h  = hh * 128 + n;
    int tap = k / 160, c = k - tap * 160;
    float v = (h < Hn && tap < 3 && c < Cn) ? W[((size_t)h * Cn + c) * 3 + tap] : 0.f;
    Wg[idx] = __float2half(v);
}

// ---------------- device helpers ----------------
__device__ __forceinline__ void ldsm4(uint32_t& r0, uint32_t& r1, uint32_t& r2,
                                      uint32_t& r3, uint32_t a) {
    asm volatile("ldmatrix.sync.aligned.m8n8.x4.shared.b16 {%0,%1,%2,%3}, [%4];"
                 : "=r"(r0), "=r"(r1), "=r"(r2), "=r"(r3) : "r"(a));
}
__device__ __forceinline__ void mma16816(float* d, uint32_t a0, uint32_t a1,
                                         uint32_t a2, uint32_t a3,
                                         uint32_t b0, uint32_t b1) {
    asm volatile(
        "mma.sync.aligned.m16n8k16.row.col.f32.f16.f16.f32 "
        "{%0,%1,%2,%3},{%4,%5,%6,%7},{%8,%9},{%0,%1,%2,%3};"
        : "+f"(d[0]), "+f"(d[1]), "+f"(d[2]), "+f"(d[3])
        : "r"(a0), "r"(a1), "r"(a2), "r"(a3), "r"(b0), "r"(b1));
}
__device__ __forceinline__ void mbar_wait(uint32_t addr, uint32_t parity) {
    asm volatile(
        "{\n\t.reg .pred P;\n\t"
        "W_%=:\n\t"
        "mbarrier.try_wait.parity.acquire.cta.shared::cta.b64 P, [%0], %1;\n\t"
        "@!P bra W_%=;\n\t}"
        :: "r"(addr), "r"(parity) : "memory");
}
__device__ __forceinline__ void expect_tx(uint32_t mbar, uint32_t bytes) {
    asm volatile("mbarrier.arrive.expect_tx.shared.b64 _, [%0], %1;"
                 :: "r"(mbar), "r"(bytes) : "memory");
}
__device__ __forceinline__ void bulk_g2s(uint32_t dst, const void* src,
                                         uint32_t bytes, uint32_t mbar) {
    asm volatile(
        "cp.async.bulk.shared::cluster.global.mbarrier::complete_tx::bytes "
        "[%0], [%1], %2, [%3];"
        :: "r"(dst), "l"(src), "r"(bytes), "r"(mbar) : "memory");
}

__device__ __forceinline__ void prefetch_unit(uint32_t sb, int u, int buf, int y) {
    int b  = y + 74 * (u >> 1);
    int mh = u & 1;
    uint32_t mbar = sb + MB_X0 + 8 * buf;
    uint32_t dst  = sb + SM_X0 + buf * XBUFB;
    const __half* src = Xg + ((size_t)(b * 2) * 130 + mh * 64) * XRS;
    expect_tx(mbar, XBUFB);
    bulk_g2s(dst,         src,             XUNIT, mbar);
    bulk_g2s(dst + XUNIT, src + 130 * XRS, XUNIT, mbar);
}

// ---------------- main: grid (2 h-halves, 74), 256 threads ----------------
__global__ __launch_bounds__(256, 1)
void pcnn_mma_kernel(const int*   __restrict__ Xmask,
                     const float* __restrict__ bias,
                     float*       __restrict__ out)
{
    extern __shared__ char smem[];
    uint32_t sb;
    asm("{ .reg .u64 t; cvta.to.shared.u64 t, %1; cvt.u32.u64 %0, t; }"
        : "=r"(sb) : "l"(smem));
    const int t    = threadIdx.x;
    const int w    = t >> 5, lane = t & 31;
    const int hh   = blockIdx.x;
    const int y    = blockIdx.y;
    const int mq   = w & 3, nh = w >> 2;
    int* ms = (int*)(smem + SM_MS);

    if (t == 0) {
        asm volatile("mbarrier.init.shared.b64 [%0], 1;" :: "r"(sb + MB_W)  : "memory");
        asm volatile("mbarrier.init.shared.b64 [%0], 1;" :: "r"(sb + MB_X0) : "memory");
        asm volatile("mbarrier.init.shared.b64 [%0], 1;" :: "r"(sb + MB_X1) : "memory");
    }
    __syncthreads();

    const int NB = (Bn - y + 73) / 74;
    const int NU = NB * 2;

    if (t == 0) {
        expect_tx(sb + MB_W, WTILE);
        bulk_g2s(sb + SM_W, Wg + (size_t)hh * 128 * WRS, WTILE, sb + MB_W);
        prefetch_unit(sb, 0, 0, y);
        if (NU > 1) prefetch_unit(sb, 1, 1, y);
    }

    // per-lane invariant address components
    const uint32_t aoff = (uint32_t)((mq * 16 + (lane & 15)) * XROWB + (lane >> 4) * 16);
    const uint32_t boff = sb + SM_W
        + (uint32_t)((nh * 64 + ((lane >> 3) & 2) * 4 + (lane & 7)) * WROWB)
        + (uint32_t)(((lane >> 3) & 1) * 16);

    int phX0 = 0, phX1 = 0;
    float pm0 = 0.f, pm1 = 0.f, pm2 = 0.f;

    mbar_wait(sb + MB_W, 0);

    for (int u = 0; u < NU; ++u) {
        const int buf = u & 1;
        const int b   = y + 74 * (u >> 1);
        const int mh  = u & 1;

        if (buf == 0) { mbar_wait(sb + MB_X0, phX0); phX0 ^= 1; }
        else          { mbar_wait(sb + MB_X1, phX1); phX1 ^= 1; }
        if (mh == 0 && t < 128) ms[t] = Xmask[b * Ln + t];
        __syncthreads();

        // ---- GEMM: m64 (this half) x n128 x K480, fp16 2-term ----
        float d[8][4];
#pragma unroll
        for (int i = 0; i < 8; ++i)
#pragma unroll
            for (int j = 0; j < 4; ++j) d[i][j] = 0.f;

        const uint32_t xb = sb + SM_X0 + buf * XBUFB;
#pragma unroll
        for (int tap = 0; tap < 3; ++tap) {
#pragma unroll
            for (int kc = 0; kc < 10; ++kc) {
                uint32_t a0, a1, a2, a3, e0, e1, e2, e3;
                uint32_t ka = (uint32_t)(tap * XROWB + kc * 32);
                ldsm4(a0, a1, a2, a3, xb + aoff + ka);             // X hi
                ldsm4(e0, e1, e2, e3, xb + XUNIT + aoff + ka);     // X lo
                uint32_t br[16];
                uint32_t kb = (uint32_t)(tap * 320 + kc * 32);
#pragma unroll
                for (int p = 0; p < 4; ++p)
                    ldsm4(br[4*p], br[4*p+1], br[4*p+2], br[4*p+3],
                          boff + p * (16 * WROWB) + kb);
#pragma unroll
                for (int p = 0; p < 4; ++p) {
                    mma16816(d[2*p],   a0, a1, a2, a3, br[4*p],   br[4*p+1]);
                    mma16816(d[2*p+1], a0, a1, a2, a3, br[4*p+2], br[4*p+3]);
                }
#pragma unroll
                for (int p = 0; p < 4; ++p) {
                    mma16816(d[2*p],   e0, e1, e2, e3, br[4*p],   br[4*p+1]);
                    mma16816(d[2*p+1], e0, e1, e2, e3, br[4*p+2], br[4*p+3]);
                }
            }
        }
        __syncthreads();

        // ---- dump acc -> Ds [64 l][132 f32] (aliases this unit's X buffer) ----
        float* Ds = (float*)(smem + SM_X0 + buf * XBUFB);
        {
            int r  = lane >> 2;
            int c0 = (lane & 3) * 2;
#pragma unroll
            for (int nt = 0; nt < 8; ++nt) {
                int col = nh * 64 + nt * 8 + c0;
                *(float2*)(Ds + (mq * 16 + r)     * 132 + col) = make_float2(d[nt][0], d[nt][1]);
                *(float2*)(Ds + (mq * 16 + r + 8) * 132 + col) = make_float2(d[nt][2], d[nt][3]);
            }
        }
        __syncthreads();

        // ---- epilogue: mask-max (+bias, floor 0) over this m-half ----
        if (t < 128) {
            int h = hh * 128 + t;
            float bb = (h < Hn) ? bias[h] : 0.f;
            if (mh == 0) { pm0 = 0.f; pm1 = 0.f; pm2 = 0.f; }
#pragma unroll 4
            for (int l = 0; l < 64; ++l) {
                float yv = Ds[l * 132 + t] + bb;
                int mk = ms[mh * 64 + l];
                if      (mk == 1) pm0 = fmaxf(pm0, yv);
                else if (mk == 2) pm1 = fmaxf(pm1, yv);
                else if (mk == 3) pm2 = fmaxf(pm2, yv);
            }
            if (mh == 1 && h < Hn) {
                float* o = out + (size_t)b * (3 * Hn) + h * 3;
                o[0] = tanhf(pm0);
                o[1] = tanhf(pm1);
                o[2] = tanhf(pm2);
            }
        }
        __syncthreads();

        if (t == 0 && u + 2 < NU) prefetch_unit(sb, u + 2, buf, y);
    }
}

extern "C" void kernel_launch(void* const* d_in, const int* in_sizes, int n_in,
                              void* d_out, int out_size)
{
    const float* Xea   = (const float*)d_in[0];
    const int*   Xmask = (const int*)  d_in[1];
    const float* W     = (const float*)d_in[2];
    const float* bias  = (const float*)d_in[3];
    float*       out   = (float*)d_out;

    xprep<<<(Bn * 130 * 21 + 255) / 256, 256>>>(Xea);
    wprep<<<(2 * 128 * WRS + 255) / 256, 256>>>(W);

    cudaFuncSetAttribute(pcnn_mma_kernel,
                         cudaFuncAttributeMaxDynamicSharedMemorySize, SMEM_BYTES);
    dim3 grid(2, 74);
    pcnn_mma_kernel<<<grid, 256, SMEM_BYTES>>>(Xmask, bias, out);
}

// round 5
// speedup vs baseline: 8.1051x; 1.8214x over previous
#include <cuda_runtime.h>
#include <cuda_fp16.h>
#include <cstdint>
#include <math.h>

#define Bn 2048
#define Ln 128
#define Cn 150
#define Hn 230

// X tile: fp16, padded rows (130 x 168 halves), row stride 336B
#define XRS   168
#define XROWB 336
#define XBUF  (130*XROWB)        // 43,680 B per batch
// W: [hh][128 n][488 k] fp16, k = tap*160 + c
#define WRS   488
#define WROWB 976
#define WTILE (128*WROWB)        // 124,928 B

// smem layout
#define MB_W   0
#define MB_X0  8
#define MB_X1  16
#define SM_MS  32                // int ms[128] (512B)
#define SM_RED 1024              // float red[4][128][3] = 6144B
#define SM_W   8192
#define SM_X0  (SM_W + WTILE)    // 133,120
#define SM_X1  (SM_X0 + XBUF)    // 176,800
#define SMEM_BYTES (SM_X1 + XBUF) // 220,480

__device__ __align__(128) __half Xg[(size_t)Bn * 130 * XRS];   // ~89 MB
__device__ __align__(128) __half Wg[2 * 128 * WRS];

// ---------------- prepass: X -> fp16 padded tiles ----------------
__global__ void xprep(const float* __restrict__ Xea) {
    int idx = blockIdx.x * blockDim.x + threadIdx.x;   // Bn*130*21
    if (idx >= Bn * 130 * 21) return;
    int g   = idx % 21;
    int row = (idx / 21) % 130;
    int b   = idx / (21 * 130);
    __align__(16) __half h8[8];
    if (row == 0 || row == 129) {
#pragma unroll
        for (int i = 0; i < 8; ++i) h8[i] = __float2half(0.f);
    } else {
        const float* src = Xea + ((size_t)b * Ln + (row - 1)) * Cn;
#pragma unroll
        for (int i = 0; i < 8; ++i) {
            int c = g * 8 + i;
            h8[i] = __float2half((c < Cn) ? src[c] : 0.f);
        }
    }
    *(uint4*)(&Xg[((size_t)b * 130 + row) * XRS + g * 8]) = *(uint4*)h8;
}

// ---------------- prepass: W -> fp16 [hh][n][k] ----------------
__global__ void wprep(const float* __restrict__ W) {
    int idx = blockIdx.x * blockDim.x + threadIdx.x;   // 2*128*488
    if (idx >= 2 * 128 * WRS) return;
    int k  = idx % WRS;
    int n  = (idx / WRS) % 128;
    int hh = idx / (WRS * 128);
    int h  = hh * 128 + n;
    int tap = k / 160, c = k - tap * 160;
    float v = (h < Hn && tap < 3 && c < Cn) ? W[((size_t)h * Cn + c) * 3 + tap] : 0.f;
    Wg[idx] = __float2half(v);
}

// ---------------- helpers ----------------
__device__ __forceinline__ void ldsm4(uint32_t* r, uint32_t a) {
    asm volatile("ldmatrix.sync.aligned.m8n8.x4.shared.b16 {%0,%1,%2,%3}, [%4];"
                 : "=r"(r[0]), "=r"(r[1]), "=r"(r[2]), "=r"(r[3]) : "r"(a));
}
__device__ __forceinline__ void mma16816(float* d, const uint32_t* a,
                                         uint32_t b0, uint32_t b1) {
    asm volatile(
        "mma.sync.aligned.m16n8k16.row.col.f32.f16.f16.f32 "
        "{%0,%1,%2,%3},{%4,%5,%6,%7},{%8,%9},{%0,%1,%2,%3};"
        : "+f"(d[0]), "+f"(d[1]), "+f"(d[2]), "+f"(d[3])
        : "r"(a[0]), "r"(a[1]), "r"(a[2]), "r"(a[3]), "r"(b0), "r"(b1));
}
__device__ __forceinline__ void mbar_wait(uint32_t addr, uint32_t parity) {
    asm volatile(
        "{\n\t.reg .pred P;\n\t"
        "W_%=:\n\t"
        "mbarrier.try_wait.parity.acquire.cta.shared::cta.b64 P, [%0], %1;\n\t"
        "@!P bra W_%=;\n\t}"
        :: "r"(addr), "r"(parity) : "memory");
}
__device__ __forceinline__ void expect_tx(uint32_t mbar, uint32_t bytes) {
    asm volatile("mbarrier.arrive.expect_tx.shared.b64 _, [%0], %1;"
                 :: "r"(mbar), "r"(bytes) : "memory");
}
__device__ __forceinline__ void bulk_g2s(uint32_t dst, const void* src,
                                         uint32_t bytes, uint32_t mbar) {
    asm volatile(
        "cp.async.bulk.shared::cluster.global.mbarrier::complete_tx::bytes "
        "[%0], [%1], %2, [%3];"
        :: "r"(dst), "l"(src), "r"(bytes), "r"(mbar) : "memory");
}
__device__ __forceinline__ void prefetch_unit(uint32_t sb, int u, int buf, int y) {
    int b = y + 74 * u;
    uint32_t mbar = sb + MB_X0 + 8 * buf;
    expect_tx(mbar, XBUF);
    bulk_g2s(sb + SM_X0 + buf * XBUF, Xg + (size_t)b * 130 * XRS, XBUF, mbar);
}

// ---------------- main: grid (2 h-halves, 74), 512 threads ----------------
__global__ __launch_bounds__(512, 1)
void pcnn_mma_kernel(const int*   __restrict__ Xmask,
                     const float* __restrict__ bias,
                     float*       __restrict__ out)
{
    extern __shared__ char smem[];
    uint32_t sb;
    asm("{ .reg .u64 t; cvta.to.shared.u64 t, %1; cvt.u32.u64 %0, t; }"
        : "=r"(sb) : "l"(smem));
    const int t    = threadIdx.x;
    const int w    = t >> 5, lane = t & 31;
    const int hh   = blockIdx.x;
    const int y    = blockIdx.y;
    const int mq   = w & 3;       // m32 chunk (rows mq*32..)
    const int nh   = w >> 2;      // n32 chunk (cols nh*32..)
    int*   ms  = (int*)(smem + SM_MS);
    float* red = (float*)(smem + SM_RED);

    if (t == 0) {
        asm volatile("mbarrier.init.shared.b64 [%0], 1;" :: "r"(sb + MB_W)  : "memory");
        asm volatile("mbarrier.init.shared.b64 [%0], 1;" :: "r"(sb + MB_X0) : "memory");
        asm volatile("mbarrier.init.shared.b64 [%0], 1;" :: "r"(sb + MB_X1) : "memory");
    }
    __syncthreads();

    const int NB = (Bn - y + 73) / 74;    // units (batches) for this CTA

    if (t == 0) {
        expect_tx(sb + MB_W, WTILE);
        bulk_g2s(sb + SM_W, Wg + (size_t)hh * 128 * WRS, WTILE, sb + MB_W);
        prefetch_unit(sb, 0, 0, y);
        if (NB > 1) prefetch_unit(sb, 1, 1, y);
    }

    // lane-invariant address parts
    const uint32_t aoff = (uint32_t)((mq * 32 + (lane & 15)) * XROWB + (lane >> 4) * 16);
    const uint32_t boff = sb + SM_W
        + (uint32_t)((nh * 32 + (lane & 7) + ((lane >> 4) << 3)) * WROWB)
        + (uint32_t)(((lane >> 3) & 1) * 16);

    int phX0 = 0, phX1 = 0;
    mbar_wait(sb + MB_W, 0);

    for (int u = 0; u < NB; ++u) {
        const int buf = u & 1;
        const int b   = y + 74 * u;

        if (buf == 0) { mbar_wait(sb + MB_X0, phX0); phX0 ^= 1; }
        else          { mbar_wait(sb + MB_X1, phX1); phX1 ^= 1; }
        __syncthreads();                       // prev epilogue fully done
        if (t < 128) ms[t] = Xmask[b * Ln + t];
        __syncthreads();

        // ---- GEMM: m128 x n128 x K480, warp tile m32 x n32 ----
        float d[2][4][4];
#pragma unroll
        for (int i = 0; i < 2; ++i)
#pragma unroll
            for (int j = 0; j < 4; ++j)
#pragma unroll
                for (int e = 0; e < 4; ++e) d[i][j][e] = 0.f;

        const uint32_t xb = sb + SM_X0 + buf * XBUF;
#pragma unroll
        for (int tap = 0; tap < 3; ++tap) {
#pragma unroll
            for (int kc = 0; kc < 10; ++kc) {
                uint32_t a[2][4], br[2][4];
                uint32_t ka = (uint32_t)(tap * XROWB + kc * 32);
                ldsm4(a[0], xb + aoff + ka);
                ldsm4(a[1], xb + aoff + 16 * XROWB + ka);
                uint32_t kb = (uint32_t)(tap * 320 + kc * 32);
                ldsm4(br[0], boff + kb);
                ldsm4(br[1], boff + 16 * WROWB + kb);
#pragma unroll
                for (int mt = 0; mt < 2; ++mt)
#pragma unroll
                    for (int p = 0; p < 2; ++p) {
                        mma16816(d[mt][2*p],     a[mt], br[p][0], br[p][1]);
                        mma16816(d[mt][2*p + 1], a[mt], br[p][2], br[p][3]);
                    }
            }
        }

        // ---- register epilogue: mask-gated max over rows ----
        float pm[3][8];
#pragma unroll
        for (int m = 0; m < 3; ++m)
#pragma unroll
            for (int c = 0; c < 8; ++c) pm[m][c] = -INFINITY;

        const int rbase = mq * 32 + (lane >> 2);
#pragma unroll
        for (int mt = 0; mt < 2; ++mt) {
            int mk0 = ms[rbase + mt * 16];
            int mk1 = ms[rbase + mt * 16 + 8];
#pragma unroll
            for (int j = 0; j < 4; ++j) {
                float* v = d[mt][j];
                if      (mk0 == 1) { pm[0][2*j] = fmaxf(pm[0][2*j], v[0]); pm[0][2*j+1] = fmaxf(pm[0][2*j+1], v[1]); }
                else if (mk0 == 2) { pm[1][2*j] = fmaxf(pm[1][2*j], v[0]); pm[1][2*j+1] = fmaxf(pm[1][2*j+1], v[1]); }
                else if (mk0 == 3) { pm[2][2*j] = fmaxf(pm[2][2*j], v[0]); pm[2][2*j+1] = fmaxf(pm[2][2*j+1], v[1]); }
                if      (mk1 == 1) { pm[0][2*j] = fmaxf(pm[0][2*j], v[2]); pm[0][2*j+1] = fmaxf(pm[0][2*j+1], v[3]); }
                else if (mk1 == 2) { pm[1][2*j] = fmaxf(pm[1][2*j], v[2]); pm[1][2*j+1] = fmaxf(pm[1][2*j+1], v[3]); }
                else if (mk1 == 3) { pm[2][2*j] = fmaxf(pm[2][2*j], v[2]); pm[2][2*j+1] = fmaxf(pm[2][2*j+1], v[3]); }
            }
        }
        // reduce across the 8 lanes sharing each column (xor 4, 8, 16)
#pragma unroll
        for (int off = 4; off <= 16; off <<= 1)
#pragma unroll
            for (int m = 0; m < 3; ++m)
#pragma unroll
                for (int c = 0; c < 8; ++c)
                    pm[m][c] = fmaxf(pm[m][c],
                                     __shfl_xor_sync(0xffffffffu, pm[m][c], off));
        if (lane < 4) {
#pragma unroll
            for (int c = 0; c < 8; ++c) {
                int col = nh * 32 + (c >> 1) * 8 + lane * 2 + (c & 1);
#pragma unroll
                for (int m = 0; m < 3; ++m)
                    red[(mq * 128 + col) * 3 + m] = pm[m][c];
            }
        }
        __syncthreads();

        if (t == 0 && u + 2 < NB) prefetch_unit(sb, u + 2, buf, y);

        if (t < 128) {
            int h = hh * 128 + t;
            if (h < Hn) {
                float bb = bias[h];
                float* o = out + (size_t)b * (3 * Hn) + h * 3;
#pragma unroll
                for (int m = 0; m < 3; ++m) {
                    float r = red[(0 * 128 + t) * 3 + m];
                    r = fmaxf(r, red[(1 * 128 + t) * 3 + m]);
                    r = fmaxf(r, red[(2 * 128 + t) * 3 + m]);
                    r = fmaxf(r, red[(3 * 128 + t) * 3 + m]);
                    o[m] = tanhf(fmaxf(0.f, r + bb));
                }
            }
        }
    }
}

extern "C" void kernel_launch(void* const* d_in, const int* in_sizes, int n_in,
                              void* d_out, int out_size)
{
    const float* Xea   = (const float*)d_in[0];
    const int*   Xmask = (const int*)  d_in[1];
    const float* W     = (const float*)d_in[2];
    const float* bias  = (const float*)d_in[3];
    float*       out   = (float*)d_out;

    xprep<<<(Bn * 130 * 21 + 255) / 256, 256>>>(Xea);
    wprep<<<(2 * 128 * WRS + 255) / 256, 256>>>(W);

    cudaFuncSetAttribute(pcnn_mma_kernel,
                         cudaFuncAttributeMaxDynamicSharedMemorySize, SMEM_BYTES);
    dim3 grid(2, 74);
    pcnn_mma_kernel<<<grid, 512, SMEM_BYTES>>>(Xmask, bias, out);
}

// round 6
// speedup vs baseline: 8.3520x; 1.0305x over previous
#include <cuda_runtime.h>
#include <cuda_fp16.h>
#include <cstdint>
#include <math.h>

#define Bn 2048
#define Ln 128
#define Cn 150
#define Hn 230

// X tile: fp16 padded rows (130 x 168 halves), row stride 336B
#define XRS   168
#define XROWB 336
#define XBUF  (130*XROWB)        // 43,680 B
// W: [hh][128 n][488 k] fp16, k = tap*160 + c
#define WRS   488
#define WROWB 976
#define WTILE (128*WROWB)        // 124,928 B

// smem layout
#define MB_W   0
#define SM_MS  32
#define SM_RED 1024              // float red[4][128][3]
#define SM_W   8192
#define SM_X0  (SM_W + WTILE)    // 133,120
#define SM_X1  (SM_X0 + XBUF)    // 176,800
#define SMEM_BYTES (SM_X1 + XBUF) // 220,480

#define NF4 10                   // float4 staged per thread (512*10*4 >= 19200)

__device__ __align__(128) __half Wg[2 * 128 * WRS];

__global__ void wprep(const float* __restrict__ W) {
    int idx = blockIdx.x * blockDim.x + threadIdx.x;   // 2*128*488
    if (idx >= 2 * 128 * WRS) return;
    int k  = idx % WRS;
    int n  = (idx / WRS) % 128;
    int hh = idx / (WRS * 128);
    int h  = hh * 128 + n;
    int tap = k / 160, c = k - tap * 160;
    float v = (h < Hn && tap < 3 && c < Cn) ? W[((size_t)h * Cn + c) * 3 + tap] : 0.f;
    Wg[idx] = __float2half(v);
}

// ---------------- helpers ----------------
__device__ __forceinline__ void ldsm4(uint32_t* r, uint32_t a) {
    asm volatile("ldmatrix.sync.aligned.m8n8.x4.shared.b16 {%0,%1,%2,%3}, [%4];"
                 : "=r"(r[0]), "=r"(r[1]), "=r"(r[2]), "=r"(r[3]) : "r"(a));
}
__device__ __forceinline__ void mma16816(float* d, const uint32_t* a,
                                         uint32_t b0, uint32_t b1) {
    asm volatile(
        "mma.sync.aligned.m16n8k16.row.col.f32.f16.f16.f32 "
        "{%0,%1,%2,%3},{%4,%5,%6,%7},{%8,%9},{%0,%1,%2,%3};"
        : "+f"(d[0]), "+f"(d[1]), "+f"(d[2]), "+f"(d[3])
        : "r"(a[0]), "r"(a[1]), "r"(a[2]), "r"(a[3]), "r"(b0), "r"(b1));
}
__device__ __forceinline__ void mbar_wait(uint32_t addr, uint32_t parity) {
    asm volatile(
        "{\n\t.reg .pred P;\n\t"
        "W_%=:\n\t"
        "mbarrier.try_wait.parity.acquire.cta.shared::cta.b64 P, [%0], %1;\n\t"
        "@!P bra W_%=;\n\t}"
        :: "r"(addr), "r"(parity) : "memory");
}

__device__ __forceinline__ void ld_stage(float4* s, const float4* src, int t) {
#pragma unroll
    for (int i = 0; i < NF4; ++i) {
        int f = t + 512 * i;
        if (f < 4800) s[i] = __ldg(src + f);
    }
}
__device__ __forceinline__ void cv_stage(const float4* s, char* buf, int t) {
#pragma unroll
    for (int i = 0; i < NF4; ++i) {
        int f = t + 512 * i;
        if (f < 4800) {
            const float v[4] = { s[i].x, s[i].y, s[i].z, s[i].w };
#pragma unroll
            for (int e = 0; e < 4; ++e) {
                int idx = 4 * f + e;
                int r = idx / 150;
                int c = idx - 150 * r;
                *(__half*)(buf + (r + 1) * XROWB + c * 2) = __float2half(v[e]);
            }
        }
    }
}

// ---------------- main: grid (2 h-halves, 74), 512 threads ----------------
__global__ __launch_bounds__(512, 1)
void pcnn_mma_kernel(const float* __restrict__ Xea,
                     const int*   __restrict__ Xmask,
                     const float* __restrict__ bias,
                     float*       __restrict__ out)
{
    extern __shared__ char smem[];
    uint32_t sb;
    asm("{ .reg .u64 t; cvta.to.shared.u64 t, %1; cvt.u32.u64 %0, t; }"
        : "=r"(sb) : "l"(smem));
    const int t    = threadIdx.x;
    const int w    = t >> 5, lane = t & 31;
    const int hh   = blockIdx.x;
    const int y    = blockIdx.y;
    const int mq   = w & 3;       // m32 chunk
    const int nh   = w >> 2;      // n32 chunk
    int*   ms  = (int*)(smem + SM_MS);
    float* red = (float*)(smem + SM_RED);

    if (t == 0) {
        asm volatile("mbarrier.init.shared.b64 [%0], 1;" :: "r"(sb + MB_W) : "memory");
    }
    __syncthreads();
    if (t == 0) {
        asm volatile("mbarrier.arrive.expect_tx.shared.b64 _, [%0], %1;"
                     :: "r"(sb + MB_W), "r"((uint32_t)WTILE) : "memory");
        asm volatile(
            "cp.async.bulk.shared::cluster.global.mbarrier::complete_tx::bytes "
            "[%0], [%1], %2, [%3];"
            :: "r"(sb + SM_W), "l"(Wg + (size_t)hh * 128 * WRS),
               "r"((uint32_t)WTILE), "r"(sb + MB_W) : "memory");
    }

    // zero both X buffers (halo rows + col padding stay zero forever)
    for (int i = t * 16; i < 2 * XBUF; i += 512 * 16)
        *(uint4*)(smem + SM_X0 + i) = make_uint4(0, 0, 0, 0);

    const int NB = (Bn - y + 73) / 74;

    // stage + convert unit 0, stage unit 1
    float4 st[NF4];
    ld_stage(st, (const float4*)(Xea + (size_t)y * 19200), t);
    __syncthreads();                         // zeroing done before conversion writes
    cv_stage(st, smem + SM_X0, t);
    if (NB > 1) ld_stage(st, (const float4*)(Xea + (size_t)(y + 74) * 19200), t);

    // lane-invariant address parts
    const uint32_t aoff = (uint32_t)((mq * 32 + (lane & 15)) * XROWB + (lane >> 4) * 16);
    const uint32_t boff = sb + SM_W
        + (uint32_t)((nh * 32 + (lane & 7) + ((lane >> 4) << 3)) * WROWB)
        + (uint32_t)(((lane >> 3) & 1) * 16);

    mbar_wait(sb + MB_W, 0);

    for (int u = 0; u < NB; ++u) {
        const int buf = u & 1;
        const int b   = y + 74 * u;

        if (t < 128) ms[t] = Xmask[b * Ln + t];
        __syncthreads();                    // conversion of buf[u] + ms visible

        // ---- GEMM m128 x n128 x K480, warp tile m32 x n32 ----
        float d[2][4][4];
#pragma unroll
        for (int i = 0; i < 2; ++i)
#pragma unroll
            for (int j = 0; j < 4; ++j)
#pragma unroll
                for (int e = 0; e < 4; ++e) d[i][j][e] = 0.f;

        const uint32_t xb = sb + SM_X0 + buf * XBUF;
#pragma unroll
        for (int tap = 0; tap < 3; ++tap) {
#pragma unroll
            for (int kc = 0; kc < 10; ++kc) {
                uint32_t a[2][4], br[2][4];
                uint32_t ka = (uint32_t)(tap * XROWB + kc * 32);
                ldsm4(a[0], xb + aoff + ka);
                ldsm4(a[1], xb + aoff + 16 * XROWB + ka);
                uint32_t kb = (uint32_t)(tap * 320 + kc * 32);
                ldsm4(br[0], boff + kb);
                ldsm4(br[1], boff + 16 * WROWB + kb);
#pragma unroll
                for (int mt = 0; mt < 2; ++mt)
#pragma unroll
                    for (int p = 0; p < 2; ++p) {
                        mma16816(d[mt][2*p],     a[mt], br[p][0], br[p][1]);
                        mma16816(d[mt][2*p + 1], a[mt], br[p][2], br[p][3]);
                    }
            }
        }

        // convert staged fp32[u+1] -> other buffer; stage fp32[u+2]
        if (u + 1 < NB) {
            cv_stage(st, smem + SM_X0 + (buf ^ 1) * XBUF, t);
            if (u + 2 < NB)
                ld_stage(st, (const float4*)(Xea + (size_t)(b + 148) * 19200), t);
        }

        // ---- register epilogue: mask-gated max ----
        float pm[3][8];
#pragma unroll
        for (int m = 0; m < 3; ++m)
#pragma unroll
            for (int c = 0; c < 8; ++c) pm[m][c] = -INFINITY;

        const int rbase = mq * 32 + (lane >> 2);
#pragma unroll
        for (int mt = 0; mt < 2; ++mt) {
            int mk0 = ms[rbase + mt * 16];
            int mk1 = ms[rbase + mt * 16 + 8];
#pragma unroll
            for (int j = 0; j < 4; ++j) {
                float* v = d[mt][j];
                if      (mk0 == 1) { pm[0][2*j] = fmaxf(pm[0][2*j], v[0]); pm[0][2*j+1] = fmaxf(pm[0][2*j+1], v[1]); }
                else if (mk0 == 2) { pm[1][2*j] = fmaxf(pm[1][2*j], v[0]); pm[1][2*j+1] = fmaxf(pm[1][2*j+1], v[1]); }
                else if (mk0 == 3) { pm[2][2*j] = fmaxf(pm[2][2*j], v[0]); pm[2][2*j+1] = fmaxf(pm[2][2*j+1], v[1]); }
                if      (mk1 == 1) { pm[0][2*j] = fmaxf(pm[0][2*j], v[2]); pm[0][2*j+1] = fmaxf(pm[0][2*j+1], v[3]); }
                else if (mk1 == 2) { pm[1][2*j] = fmaxf(pm[1][2*j], v[2]); pm[1][2*j+1] = fmaxf(pm[1][2*j+1], v[3]); }
                else if (mk1 == 3) { pm[2][2*j] = fmaxf(pm[2][2*j], v[2]); pm[2][2*j+1] = fmaxf(pm[2][2*j+1], v[3]); }
            }
        }
#pragma unroll
        for (int off = 4; off <= 16; off <<= 1)
#pragma unroll
            for (int m = 0; m < 3; ++m)
#pragma unroll
                for (int c = 0; c < 8; ++c)
                    pm[m][c] = fmaxf(pm[m][c],
                                     __shfl_xor_sync(0xffffffffu, pm[m][c], off));
        if (lane < 4) {
#pragma unroll
            for (int c = 0; c < 8; ++c) {
                int col = nh * 32 + (c >> 1) * 8 + lane * 2 + (c & 1);
#pragma unroll
                for (int m = 0; m < 3; ++m)
                    red[(mq * 128 + col) * 3 + m] = pm[m][c];
            }
        }
        __syncthreads();

        if (t < 128) {
            int h = hh * 128 + t;
            if (h < Hn) {
                float bb = bias[h];
                float* o = out + (size_t)b * (3 * Hn) + h * 3;
#pragma unroll
                for (int m = 0; m < 3; ++m) {
                    float r = red[(0 * 128 + t) * 3 + m];
                    r = fmaxf(r, red[(1 * 128 + t) * 3 + m]);
                    r = fmaxf(r, red[(2 * 128 + t) * 3 + m]);
                    r = fmaxf(r, red[(3 * 128 + t) * 3 + m]);
                    o[m] = tanhf(fmaxf(0.f, r + bb));
                }
            }
        }
        __syncthreads();   // out reads red; conversion for next unit already done
    }
}

extern "C" void kernel_launch(void* const* d_in, const int* in_sizes, int n_in,
                              void* d_out, int out_size)
{
    const float* Xea   = (const float*)d_in[0];
    const int*   Xmask = (const int*)  d_in[1];
    const float* W     = (const float*)d_in[2];
    const float* bias  = (const float*)d_in[3];
    float*       out   = (float*)d_out;

    wprep<<<(2 * 128 * WRS + 255) / 256, 256>>>(W);

    cudaFuncSetAttribute(pcnn_mma_kernel,
                         cudaFuncAttributeMaxDynamicSharedMemorySize, SMEM_BYTES);
    dim3 grid(2, 74);
    pcnn_mma_kernel<<<grid, 512, SMEM_BYTES>>>(Xea, Xmask, bias, out);
}

// round 7
// speedup vs baseline: 8.4546x; 1.0123x over previous
#include <cuda_runtime.h>
#include <cuda_fp16.h>
#include <cstdint>
#include <math.h>

#define Bn 2048
#define Ln 128
#define Cn 150
#define Hn 230

// X tile: fp16 padded rows (130 x 168 halves), row stride 336B
#define XRS   168
#define XROWB 336
#define XBUF  (130*XROWB)        // 43,680 B
// W: [hh][128 n][488 k] fp16, k = tap*160 + c
#define WRS   488
#define WROWB 976
#define WTILE (128*WROWB)        // 124,928 B

// smem layout
#define MB_W   0
#define SM_MS  32
#define SM_RED 1024              // float red[4][128][3]
#define SM_W   8192
#define SM_X0  (SM_W + WTILE)    // 133,120
#define SM_X1  (SM_X0 + XBUF)    // 176,800
#define SMEM_BYTES (SM_X1 + XBUF) // 220,480

__device__ __align__(128) __half Wg[2 * 128 * WRS];

__global__ void wprep(const float* __restrict__ W) {
    int idx = blockIdx.x * blockDim.x + threadIdx.x;   // 2*128*488
    if (idx >= 2 * 128 * WRS) return;
    int k  = idx % WRS;
    int n  = (idx / WRS) % 128;
    int hh = idx / (WRS * 128);
    int h  = hh * 128 + n;
    int tap = k / 160, c = k - tap * 160;
    float v = (h < Hn && tap < 3 && c < Cn) ? W[((size_t)h * Cn + c) * 3 + tap] : 0.f;
    Wg[idx] = __float2half(v);
}

// ---------------- helpers ----------------
__device__ __forceinline__ void ldsm4(uint32_t* r, uint32_t a) {
    asm volatile("ldmatrix.sync.aligned.m8n8.x4.shared.b16 {%0,%1,%2,%3}, [%4];"
                 : "=r"(r[0]), "=r"(r[1]), "=r"(r[2]), "=r"(r[3]) : "r"(a));
}
__device__ __forceinline__ void mma16816(float* d, const uint32_t* a,
                                         uint32_t b0, uint32_t b1) {
    asm volatile(
        "mma.sync.aligned.m16n8k16.row.col.f32.f16.f16.f32 "
        "{%0,%1,%2,%3},{%4,%5,%6,%7},{%8,%9},{%0,%1,%2,%3};"
        : "+f"(d[0]), "+f"(d[1]), "+f"(d[2]), "+f"(d[3])
        : "r"(a[0]), "r"(a[1]), "r"(a[2]), "r"(a[3]), "r"(b0), "r"(b1));
}
__device__ __forceinline__ void mbar_wait(uint32_t addr, uint32_t parity) {
    asm volatile(
        "{\n\t.reg .pred P;\n\t"
        "W_%=:\n\t"
        "mbarrier.try_wait.parity.acquire.cta.shared::cta.b64 P, [%0], %1;\n\t"
        "@!P bra W_%=;\n\t}"
        :: "r"(addr), "r"(parity) : "memory");
}

// staged fp32 -> fp16 tile store (half2 pairs; c always even, pairs never cross rows)
__device__ __forceinline__ void cv_store(const float4* st, char* buf, int t) {
#pragma unroll
    for (int i = 0; i < 10; ++i) {
        int f = t + 512 * i;
        if (f < 4800) {
            int idx = 4 * f;
            int r = idx / 150;
            int c = idx - 150 * r;
            __half2 p0 = __floats2half2_rn(st[i].x, st[i].y);
            __half2 p1 = __floats2half2_rn(st[i].z, st[i].w);
            *(__half2*)(buf + (r + 1) * XROWB + c * 2) = p0;
            int c2 = c + 2, r2 = r;
            if (c2 >= 150) { c2 -= 150; r2 += 1; }
            *(__half2*)(buf + (r2 + 1) * XROWB + c2 * 2) = p1;
        }
    }
}
__device__ __forceinline__ void ld_stage(float4* st, const float4* src, int t) {
#pragma unroll
    for (int i = 0; i < 10; ++i) {
        int f = t + 512 * i;
        if (f < 4800) st[i] = __ldg(src + f);
    }
}

// ---------------- main: grid (2 h-halves, 74), 512 threads ----------------
__global__ __launch_bounds__(512, 1)
void pcnn_mma_kernel(const float* __restrict__ Xea,
                     const int*   __restrict__ Xmask,
                     const float* __restrict__ bias,
                     float*       __restrict__ out)
{
    extern __shared__ char smem[];
    uint32_t sb;
    asm("{ .reg .u64 t; cvta.to.shared.u64 t, %1; cvt.u32.u64 %0, t; }"
        : "=r"(sb) : "l"(smem));
    const int t    = threadIdx.x;
    const int w    = t >> 5, lane = t & 31;
    const int hh   = blockIdx.x;
    const int y    = blockIdx.y;
    const int mq   = w & 3;       // m32 chunk
    const int nh   = w >> 2;      // n32 chunk
    int*   ms  = (int*)(smem + SM_MS);
    float* red = (float*)(smem + SM_RED);

    if (t == 0) {
        asm volatile("mbarrier.init.shared.b64 [%0], 1;" :: "r"(sb + MB_W) : "memory");
    }
    __syncthreads();
    if (t == 0) {
        asm volatile("mbarrier.arrive.expect_tx.shared.b64 _, [%0], %1;"
                     :: "r"(sb + MB_W), "r"((uint32_t)WTILE) : "memory");
        asm volatile(
            "cp.async.bulk.shared::cluster.global.mbarrier::complete_tx::bytes "
            "[%0], [%1], %2, [%3];"
            :: "r"(sb + SM_W), "l"(Wg + (size_t)hh * 128 * WRS),
               "r"((uint32_t)WTILE), "r"(sb + MB_W) : "memory");
    }

    // zero both X buffers (halo rows + col padding stay zero forever)
    for (int i = t * 16; i < 2 * XBUF; i += 512 * 16)
        *(uint4*)(smem + SM_X0 + i) = make_uint4(0, 0, 0, 0);

    const int NB = (Bn - y + 73) / 74;

    // convert unit 0 into buf0
    {
        float4 st[10];
        ld_stage(st, (const float4*)(Xea + (size_t)y * 19200), t);
        __syncthreads();                 // zeroing done before conversion writes
        cv_store(st, smem + SM_X0, t);
    }

    // lane-invariant address parts
    const uint32_t aoff = (uint32_t)((mq * 32 + (lane & 15)) * XROWB + (lane >> 4) * 16);
    const uint32_t boff = sb + SM_W
        + (uint32_t)((nh * 32 + (lane & 7) + ((lane >> 4) << 3)) * WROWB)
        + (uint32_t)(((lane >> 3) & 1) * 16);

    mbar_wait(sb + MB_W, 0);

    for (int u = 0; u < NB; ++u) {
        const int buf = u & 1;
        const int b   = y + 74 * u;

        if (t < 128) ms[t] = Xmask[b * Ln + t];
        __syncthreads();     // cv of buf[u] + ms visible; red reads of prev unit done

        // ---- GEMM m128 x n128 x K480, warp m32 x n32, 2-stage k pipeline ----
        float d[2][4][4];
#pragma unroll
        for (int i = 0; i < 2; ++i)
#pragma unroll
            for (int j = 0; j < 4; ++j)
#pragma unroll
                for (int e = 0; e < 4; ++e) d[i][j][e] = 0.f;

        const uint32_t xb = sb + SM_X0 + buf * XBUF;
        uint32_t af[2][8], bf[2][8];
        ldsm4(&af[0][0], xb + aoff);
        ldsm4(&af[0][4], xb + aoff + 16 * XROWB);
        ldsm4(&bf[0][0], boff);
        ldsm4(&bf[0][4], boff + 16 * WROWB);
#pragma unroll
        for (int kk = 0; kk < 30; ++kk) {
            const int cur = kk & 1, nxt = cur ^ 1;
            if (kk < 29) {
                const int tapn = (kk + 1) / 10, kcn = (kk + 1) % 10;
                const uint32_t kan = (uint32_t)(tapn * XROWB + kcn * 32);
                const uint32_t kbn = (uint32_t)(tapn * 320 + kcn * 32);
                ldsm4(&af[nxt][0], xb + aoff + kan);
                ldsm4(&af[nxt][4], xb + aoff + 16 * XROWB + kan);
                ldsm4(&bf[nxt][0], boff + kbn);
                ldsm4(&bf[nxt][4], boff + 16 * WROWB + kbn);
            }
#pragma unroll
            for (int mt = 0; mt < 2; ++mt)
#pragma unroll
                for (int p = 0; p < 2; ++p) {
                    mma16816(d[mt][2*p],     &af[cur][mt*4], bf[cur][p*4],   bf[cur][p*4+1]);
                    mma16816(d[mt][2*p + 1], &af[cur][mt*4], bf[cur][p*4+2], bf[cur][p*4+3]);
                }
        }

        // ---- issue next unit's fp32 loads (consumed after epilogue) ----
        float4 st[10];
        if (u + 1 < NB)
            ld_stage(st, (const float4*)(Xea + (size_t)(b + 74) * 19200), t);

        // ---- register epilogue: mask-gated max ----
        float pm[3][8];
#pragma unroll
        for (int m = 0; m < 3; ++m)
#pragma unroll
            for (int c = 0; c < 8; ++c) pm[m][c] = -INFINITY;

        const int rbase = mq * 32 + (lane >> 2);
#pragma unroll
        for (int mt = 0; mt < 2; ++mt) {
            int mk0 = ms[rbase + mt * 16];
            int mk1 = ms[rbase + mt * 16 + 8];
#pragma unroll
            for (int j = 0; j < 4; ++j) {
                float* v = d[mt][j];
                if      (mk0 == 1) { pm[0][2*j] = fmaxf(pm[0][2*j], v[0]); pm[0][2*j+1] = fmaxf(pm[0][2*j+1], v[1]); }
                else if (mk0 == 2) { pm[1][2*j] = fmaxf(pm[1][2*j], v[0]); pm[1][2*j+1] = fmaxf(pm[1][2*j+1], v[1]); }
                else if (mk0 == 3) { pm[2][2*j] = fmaxf(pm[2][2*j], v[0]); pm[2][2*j+1] = fmaxf(pm[2][2*j+1], v[1]); }
                if      (mk1 == 1) { pm[0][2*j] = fmaxf(pm[0][2*j], v[2]); pm[0][2*j+1] = fmaxf(pm[0][2*j+1], v[3]); }
                else if (mk1 == 2) { pm[1][2*j] = fmaxf(pm[1][2*j], v[2]); pm[1][2*j+1] = fmaxf(pm[1][2*j+1], v[3]); }
                else if (mk1 == 3) { pm[2][2*j] = fmaxf(pm[2][2*j], v[2]); pm[2][2*j+1] = fmaxf(pm[2][2*j+1], v[3]); }
            }
        }
#pragma unroll
        for (int off = 4; off <= 16; off <<= 1)
#pragma unroll
            for (int m = 0; m < 3; ++m)
#pragma unroll
                for (int c = 0; c < 8; ++c)
                    pm[m][c] = fmaxf(pm[m][c],
                                     __shfl_xor_sync(0xffffffffu, pm[m][c], off));
        if (lane < 4) {
#pragma unroll
            for (int c = 0; c < 8; ++c) {
                int col = nh * 32 + (c >> 1) * 8 + lane * 2 + (c & 1);
#pragma unroll
                for (int m = 0; m < 3; ++m)
                    red[(mq * 128 + col) * 3 + m] = pm[m][c];
            }
        }
        __syncthreads();     // red visible

        if (t < 128) {
            int h = hh * 128 + t;
            if (h < Hn) {
                float bb = bias[h];
                float* o = out + (size_t)b * (3 * Hn) + h * 3;
#pragma unroll
                for (int m = 0; m < 3; ++m) {
                    float r = red[(0 * 128 + t) * 3 + m];
                    r = fmaxf(r, red[(1 * 128 + t) * 3 + m]);
                    r = fmaxf(r, red[(2 * 128 + t) * 3 + m]);
                    r = fmaxf(r, red[(3 * 128 + t) * 3 + m]);
                    o[m] = tanhf(fmaxf(0.f, r + bb));
                }
            }
        }

        // ---- convert staged fp32 -> buf[u+1] (covered by next top sync) ----
        if (u + 1 < NB)
            cv_store(st, smem + SM_X0 + (buf ^ 1) * XBUF, t);
    }
}

extern "C" void kernel_launch(void* const* d_in, const int* in_sizes, int n_in,
                              void* d_out, int out_size)
{
    const float* Xea   = (const float*)d_in[0];
    const int*   Xmask = (const int*)  d_in[1];
    const float* W     = (const float*)d_in[2];
    const float* bias  = (const float*)d_in[3];
    float*       out   = (float*)d_out;

    wprep<<<(2 * 128 * WRS + 255) / 256, 256>>>(W);

    cudaFuncSetAttribute(pcnn_mma_kernel,
                         cudaFuncAttributeMaxDynamicSharedMemorySize, SMEM_BYTES);
    dim3 grid(2, 74);
    pcnn_mma_kernel<<<grid, 512, SMEM_BYTES>>>(Xea, Xmask, bias, out);
}

// round 8
// speedup vs baseline: 8.4948x; 1.0048x over previous
#include <cuda_runtime.h>
#include <cuda_fp16.h>
#include <cstdint>
#include <math.h>

#define Bn 2048
#define Ln 128
#define Cn 150
#define Hn 230

// X tile: fp16 padded rows (130 x 168 halves), row stride 336B
#define XRS   168
#define XROWB 336
#define XBUF  (130*XROWB)        // 43,680 B
// W: [hh][128 n][488 k] fp16, k = tap*160 + c
#define WRS   488
#define WROWB 976
#define WTILE (128*WROWB)        // 124,928 B

// smem layout
#define MB_W    0
#define SM_WC   32               // int wcnt[4]
#define SM_ACT  48               // uint8 act[128]
#define SM_PMS  176              // uint8 pms[128]
#define SM_RED  1024             // float red[4][128][3]
#define SM_W    8192
#define SM_X0   (SM_W + WTILE)   // 133,120
#define SM_X1   (SM_X0 + XBUF)   // 176,800
#define SMEM_BYTES (SM_X1 + XBUF) // 220,480

__device__ __align__(128) __half Wg[2 * 128 * WRS];

__global__ void wprep(const float* __restrict__ W) {
    int idx = blockIdx.x * blockDim.x + threadIdx.x;   // 2*128*488
    if (idx >= 2 * 128 * WRS) return;
    int k  = idx % WRS;
    int n  = (idx / WRS) % 128;
    int hh = idx / (WRS * 128);
    int h  = hh * 128 + n;
    int tap = k / 160, c = k - tap * 160;
    float v = (h < Hn && tap < 3 && c < Cn) ? W[((size_t)h * Cn + c) * 3 + tap] : 0.f;
    Wg[idx] = __float2half(v);
}

// ---------------- helpers ----------------
__device__ __forceinline__ void ldsm4(uint32_t* r, uint32_t a) {
    asm volatile("ldmatrix.sync.aligned.m8n8.x4.shared.b16 {%0,%1,%2,%3}, [%4];"
                 : "=r"(r[0]), "=r"(r[1]), "=r"(r[2]), "=r"(r[3]) : "r"(a));
}
__device__ __forceinline__ void mma16816(float* d, const uint32_t* a,
                                         uint32_t b0, uint32_t b1) {
    asm volatile(
        "mma.sync.aligned.m16n8k16.row.col.f32.f16.f16.f32 "
        "{%0,%1,%2,%3},{%4,%5,%6,%7},{%8,%9},{%0,%1,%2,%3};"
        : "+f"(d[0]), "+f"(d[1]), "+f"(d[2]), "+f"(d[3])
        : "r"(a[0]), "r"(a[1]), "r"(a[2]), "r"(a[3]), "r"(b0), "r"(b1));
}
__device__ __forceinline__ void mbar_wait(uint32_t addr, uint32_t parity) {
    asm volatile(
        "{\n\t.reg .pred P;\n\t"
        "W_%=:\n\t"
        "mbarrier.try_wait.parity.acquire.cta.shared::cta.b64 P, [%0], %1;\n\t"
        "@!P bra W_%=;\n\t}"
        :: "r"(addr), "r"(parity) : "memory");
}

// staged fp32 -> fp16 tile store (half2 pairs; c always even, pairs never cross rows)
__device__ __forceinline__ void cv_store(const float4* st, char* buf, int t) {
#pragma unroll
    for (int i = 0; i < 10; ++i) {
        int f = t + 512 * i;
        if (f < 4800) {
            int idx = 4 * f;
            int r = idx / 150;
            int c = idx - 150 * r;
            __half2 p0 = __floats2half2_rn(st[i].x, st[i].y);
            __half2 p1 = __floats2half2_rn(st[i].z, st[i].w);
            *(__half2*)(buf + (r + 1) * XROWB + c * 2) = p0;
            int c2 = c + 2, r2 = r;
            if (c2 >= 150) { c2 -= 150; r2 += 1; }
            *(__half2*)(buf + (r2 + 1) * XROWB + c2 * 2) = p1;
        }
    }
}
__device__ __forceinline__ void ld_stage(float4* st, const float4* src, int t) {
#pragma unroll
    for (int i = 0; i < 10; ++i) {
        int f = t + 512 * i;
        if (f < 4800) st[i] = __ldg(src + f);
    }
}

// GEMM k-loop over active rows: MT = number of m16 tiles this warp runs (1 or 2)
template<int MT>
__device__ __forceinline__ void gemm_run(uint32_t A0, uint32_t A1, uint32_t boff,
                                         float d[2][4][4]) {
    uint32_t af[2][8], bf[2][8];
    ldsm4(&af[0][0], A0);
    if (MT == 2) ldsm4(&af[0][4], A1);
    ldsm4(&bf[0][0], boff);
    ldsm4(&bf[0][4], boff + 16 * WROWB);
#pragma unroll
    for (int kk = 0; kk < 30; ++kk) {
        const int cur = kk & 1, nxt = cur ^ 1;
        if (kk < 29) {
            const int tapn = (kk + 1) / 10, kcn = (kk + 1) % 10;
            const uint32_t kan = (uint32_t)(tapn * XROWB + kcn * 32);
            const uint32_t kbn = (uint32_t)(tapn * 320 + kcn * 32);
            ldsm4(&af[nxt][0], A0 + kan);
            if (MT == 2) ldsm4(&af[nxt][4], A1 + kan);
            ldsm4(&bf[nxt][0], boff + kbn);
            ldsm4(&bf[nxt][4], boff + 16 * WROWB + kbn);
        }
#pragma unroll
        for (int mt = 0; mt < MT; ++mt)
#pragma unroll
            for (int p = 0; p < 2; ++p) {
                mma16816(d[mt][2*p],     &af[cur][mt*4], bf[cur][p*4],   bf[cur][p*4+1]);
                mma16816(d[mt][2*p + 1], &af[cur][mt*4], bf[cur][p*4+2], bf[cur][p*4+3]);
            }
    }
}

// ---------------- main: grid (2 h-halves, 74), 512 threads ----------------
__global__ __launch_bounds__(512, 1)
void pcnn_mma_kernel(const float* __restrict__ Xea,
                     const int*   __restrict__ Xmask,
                     const float* __restrict__ bias,
                     float*       __restrict__ out)
{
    extern __shared__ char smem[];
    uint32_t sb;
    asm("{ .reg .u64 t; cvta.to.shared.u64 t, %1; cvt.u32.u64 %0, t; }"
        : "=r"(sb) : "l"(smem));
    const int t    = threadIdx.x;
    const int w    = t >> 5, lane = t & 31;
    const int hh   = blockIdx.x;
    const int y    = blockIdx.y;
    const int nh   = w >> 2;                      // n32 chunk
    const int mq   = ((w & 3) + nh) & 3;          // m32 chunk (Latin square vs SMSP)
    int*     wcnt = (int*)(smem + SM_WC);
    uint8_t* act  = (uint8_t*)(smem + SM_ACT);
    uint8_t* pms  = (uint8_t*)(smem + SM_PMS);
    float*   red  = (float*)(smem + SM_RED);

    if (t == 0) {
        asm volatile("mbarrier.init.shared.b64 [%0], 1;" :: "r"(sb + MB_W) : "memory");
    }
    __syncthreads();
    if (t == 0) {
        asm volatile("mbarrier.arrive.expect_tx.shared.b64 _, [%0], %1;"
                     :: "r"(sb + MB_W), "r"((uint32_t)WTILE) : "memory");
        asm volatile(
            "cp.async.bulk.shared::cluster.global.mbarrier::complete_tx::bytes "
            "[%0], [%1], %2, [%3];"
            :: "r"(sb + SM_W), "l"(Wg + (size_t)hh * 128 * WRS),
               "r"((uint32_t)WTILE), "r"(sb + MB_W) : "memory");
    }

    // zero both X buffers (halo rows + col padding stay zero forever)
    for (int i = t * 16; i < 2 * XBUF; i += 512 * 16)
        *(uint4*)(smem + SM_X0 + i) = make_uint4(0, 0, 0, 0);

    const int NB = (Bn - y + 73) / 74;

    // convert unit 0 into buf0
    {
        float4 st[10];
        ld_stage(st, (const float4*)(Xea + (size_t)y * 19200), t);
        __syncthreads();                 // zeroing done before conversion writes
        cv_store(st, smem + SM_X0, t);
    }

    // lane-invariant B address
    const uint32_t boff = sb + SM_W
        + (uint32_t)((nh * 32 + (lane & 7) + ((lane >> 4) << 3)) * WROWB)
        + (uint32_t)(((lane >> 3) & 1) * 16);

    mbar_wait(sb + MB_W, 0);

    for (int u = 0; u < NB; ++u) {
        const int buf = u & 1;
        const int b   = y + 74 * u;

        // ---- mask compaction (active rows only) ----
        int mk = 0;
        unsigned bal = 0;
        if (t < 128) {
            mk  = Xmask[b * Ln + t];
            bal = __ballot_sync(0xffffffffu, mk != 0);
            if ((t & 31) == 0) wcnt[t >> 5] = __popc(bal);
        }
        __syncthreads();   // wcnt ready; cv of buf[u] visible; prev red reads done
        const int c0 = wcnt[0], c1 = wcnt[1], c2 = wcnt[2], c3 = wcnt[3];
        const int na = c0 + c1 + c2 + c3;
        if (t < 128) {
            int wofs = (t >= 32 ? c0 : 0) + (t >= 64 ? c1 : 0) + (t >= 96 ? c2 : 0);
            if (mk != 0) {
                int r = wofs + __popc(bal & ((1u << (t & 31)) - 1u));
                act[r] = (uint8_t)t;
                pms[r] = (uint8_t)mk;
            }
            if (t >= na) { act[t] = 0; pms[t] = 0; }
        }
        __syncthreads();   // act/pms ready

        // ---- GEMM over compacted rows: m=na x n128 x K480 ----
        float d[2][4][4];
#pragma unroll
        for (int i = 0; i < 2; ++i)
#pragma unroll
            for (int j = 0; j < 4; ++j)
#pragma unroll
                for (int e = 0; e < 4; ++e) d[i][j][e] = 0.f;

        const uint32_t xb = sb + SM_X0 + buf * XBUF;
        const int r0 = mq * 32 + (lane & 15);
        const uint32_t colp = (uint32_t)((lane >> 4) << 4);
        const uint32_t A0 = xb + (uint32_t)act[r0]      * XROWB + colp;
        const uint32_t A1 = xb + (uint32_t)act[r0 + 16] * XROWB + colp;
        const int myrows = na - mq * 32;
        if (myrows > 16)     gemm_run<2>(A0, A1, boff, d);
        else if (myrows > 0) gemm_run<1>(A0, A1, boff, d);

        // ---- issue next unit's fp32 loads (consumed after epilogue) ----
        float4 st[10];
        if (u + 1 < NB)
            ld_stage(st, (const float4*)(Xea + (size_t)(b + 74) * 19200), t);

        // ---- register epilogue: mask-gated max over compacted rows ----
        float pm[3][8];
#pragma unroll
        for (int m = 0; m < 3; ++m)
#pragma unroll
            for (int c = 0; c < 8; ++c) pm[m][c] = -INFINITY;

        const int rbase = mq * 32 + (lane >> 2);
#pragma unroll
        for (int mt = 0; mt < 2; ++mt) {
            int mk0 = pms[rbase + mt * 16];
            int mk1 = pms[rbase + mt * 16 + 8];
#pragma unroll
            for (int j = 0; j < 4; ++j) {
                float* v = d[mt][j];
                if      (mk0 == 1) { pm[0][2*j] = fmaxf(pm[0][2*j], v[0]); pm[0][2*j+1] = fmaxf(pm[0][2*j+1], v[1]); }
                else if (mk0 == 2) { pm[1][2*j] = fmaxf(pm[1][2*j], v[0]); pm[1][2*j+1] = fmaxf(pm[1][2*j+1], v[1]); }
                else if (mk0 == 3) { pm[2][2*j] = fmaxf(pm[2][2*j], v[0]); pm[2][2*j+1] = fmaxf(pm[2][2*j+1], v[1]); }
                if      (mk1 == 1) { pm[0][2*j] = fmaxf(pm[0][2*j], v[2]); pm[0][2*j+1] = fmaxf(pm[0][2*j+1], v[3]); }
                else if (mk1 == 2) { pm[1][2*j] = fmaxf(pm[1][2*j], v[2]); pm[1][2*j+1] = fmaxf(pm[1][2*j+1], v[3]); }
                else if (mk1 == 3) { pm[2][2*j] = fmaxf(pm[2][2*j], v[2]); pm[2][2*j+1] = fmaxf(pm[2][2*j+1], v[3]); }
            }
        }
#pragma unroll
        for (int off = 4; off <= 16; off <<= 1)
#pragma unroll
            for (int m = 0; m < 3; ++m)
#pragma unroll
                for (int c = 0; c < 8; ++c)
                    pm[m][c] = fmaxf(pm[m][c],
                                     __shfl_xor_sync(0xffffffffu, pm[m][c], off));
        if (lane < 4) {
#pragma unroll
            for (int c = 0; c < 8; ++c) {
                int col = nh * 32 + (c >> 1) * 8 + lane * 2 + (c & 1);
#pragma unroll
                for (int m = 0; m < 3; ++m)
                    red[(mq * 128 + col) * 3 + m] = pm[m][c];
            }
        }
        __syncthreads();     // red visible

        if (t < 128) {
            int h = hh * 128 + t;
            if (h < Hn) {
                float bb = bias[h];
                float* o = out + (size_t)b * (3 * Hn) + h * 3;
#pragma unroll
                for (int m = 0; m < 3; ++m) {
                    float r = red[(0 * 128 + t) * 3 + m];
                    r = fmaxf(r, red[(1 * 128 + t) * 3 + m]);
                    r = fmaxf(r, red[(2 * 128 + t) * 3 + m]);
                    r = fmaxf(r, red[(3 * 128 + t) * 3 + m]);
                    o[m] = tanhf(fmaxf(0.f, r + bb));
                }
            }
        }

        // ---- convert staged fp32 -> buf[u+1] (covered by next unit's sync) ----
        if (u + 1 < NB)
            cv_store(st, smem + SM_X0 + (buf ^ 1) * XBUF, t);
    }
}

extern "C" void kernel_launch(void* const* d_in, const int* in_sizes, int n_in,
                              void* d_out, int out_size)
{
    const float* Xea   = (const float*)d_in[0];
    const int*   Xmask = (const int*)  d_in[1];
    const float* W     = (const float*)d_in[2];
    const float* bias  = (const float*)d_in[3];
    float*       out   = (float*)d_out;

    wprep<<<(2 * 128 * WRS + 255) / 256, 256>>>(W);

    cudaFuncSetAttribute(pcnn_mma_kernel,
                         cudaFuncAttributeMaxDynamicSharedMemorySize, SMEM_BYTES);
    dim3 grid(2, 74);
    pcnn_mma_kernel<<<grid, 512, SMEM_BYTES>>>(Xea, Xmask, bias, out);
}

// round 9
// speedup vs baseline: 8.9614x; 1.0549x over previous
#include <cuda_runtime.h>
#include <cuda_fp16.h>
#include <cstdint>
#include <math.h>

#define Bn 2048
#define Ln 128
#define Cn 150
#define Hn 230

// X tile: fp16 padded rows (130 x 168 halves), row stride 336B
#define XRS   168
#define XROWB 336
#define XBUF  (130*XROWB)        // 43,680 B
// W: [hh][128 n][488 k] fp16, k = tap*160 + c
#define WRS   488
#define WROWB 976
#define WTILE (128*WROWB)        // 124,928 B

#define THREADS 384

// smem layout
#define MB_W    0
#define SM_WC   16               // int wcnt[2][4]
#define SM_ACT  64               // uint8 act[2][128]
#define SM_PMS  320              // uint8 pms[2][128]
#define SM_RED  1024             // float red[2][128][3] = 3072B
#define SM_W    4096
#define SM_X0   (SM_W + WTILE)   // 129,024
#define SM_X1   (SM_X0 + XBUF)   // 172,704
#define SMEM_BYTES (SM_X1 + XBUF) // 216,384

__device__ __align__(128) __half Wg[2 * 128 * WRS];

__global__ void wprep(const float* __restrict__ W) {
    int idx = blockIdx.x * blockDim.x + threadIdx.x;   // 2*128*488
    if (idx >= 2 * 128 * WRS) return;
    int k  = idx % WRS;
    int n  = (idx / WRS) % 128;
    int hh = idx / (WRS * 128);
    int h  = hh * 128 + n;
    int tap = k / 160, c = k - tap * 160;
    float v = (h < Hn && tap < 3 && c < Cn) ? W[((size_t)h * Cn + c) * 3 + tap] : 0.f;
    Wg[idx] = __float2half(v);
}

// ---------------- helpers ----------------
__device__ __forceinline__ void ldsm4(uint32_t* r, uint32_t a) {
    asm volatile("ldmatrix.sync.aligned.m8n8.x4.shared.b16 {%0,%1,%2,%3}, [%4];"
                 : "=r"(r[0]), "=r"(r[1]), "=r"(r[2]), "=r"(r[3]) : "r"(a));
}
__device__ __forceinline__ void mma16816(float* d, const uint32_t* a,
                                         uint32_t b0, uint32_t b1) {
    asm volatile(
        "mma.sync.aligned.m16n8k16.row.col.f32.f16.f16.f32 "
        "{%0,%1,%2,%3},{%4,%5,%6,%7},{%8,%9},{%0,%1,%2,%3};"
        : "+f"(d[0]), "+f"(d[1]), "+f"(d[2]), "+f"(d[3])
        : "r"(a[0]), "r"(a[1]), "r"(a[2]), "r"(a[3]), "r"(b0), "r"(b1));
}
__device__ __forceinline__ void mbar_wait(uint32_t addr, uint32_t parity) {
    asm volatile(
        "{\n\t.reg .pred P;\n\t"
        "W_%=:\n\t"
        "mbarrier.try_wait.parity.acquire.cta.shared::cta.b64 P, [%0], %1;\n\t"
        "@!P bra W_%=;\n\t}"
        :: "r"(addr), "r"(parity) : "memory");
}

// GEMM k-loop, m64n32 warp tile, MT = active m16 tiles (1..4)
template<int MT>
__device__ __forceinline__ void gemm_run(const uint32_t* A, uint32_t boff,
                                         float (*d)[4][4]) {
    uint32_t af[2][4][4], bf[2][8];
#pragma unroll
    for (int mt = 0; mt < MT; ++mt) ldsm4(af[0][mt], A[mt]);
    ldsm4(&bf[0][0], boff);
    ldsm4(&bf[0][4], boff + 16 * WROWB);
#pragma unroll
    for (int kk = 0; kk < 30; ++kk) {
        const int cur = kk & 1, nxt = cur ^ 1;
        if (kk < 29) {
            const int tapn = (kk + 1) / 10, kcn = (kk + 1) % 10;
            const uint32_t kan = (uint32_t)(tapn * XROWB + kcn * 32);
            const uint32_t kbn = (uint32_t)(tapn * 320 + kcn * 32);
#pragma unroll
            for (int mt = 0; mt < MT; ++mt) ldsm4(af[nxt][mt], A[mt] + kan);
            ldsm4(&bf[nxt][0], boff + kbn);
            ldsm4(&bf[nxt][4], boff + 16 * WROWB + kbn);
        }
#pragma unroll
        for (int mt = 0; mt < MT; ++mt)
#pragma unroll
            for (int pp = 0; pp < 2; ++pp) {
                mma16816(d[mt][2*pp],     af[cur][mt], bf[cur][pp*4],   bf[cur][pp*4+1]);
                mma16816(d[mt][2*pp + 1], af[cur][mt], bf[cur][pp*4+2], bf[cur][pp*4+3]);
            }
    }
}

// producer warps: stage fp32 X -> fp16 tile, compact mask (slot-double-buffered)
__device__ __forceinline__ void stage_unit(char* smem, const float* __restrict__ Xea,
                                           const int* __restrict__ Xmask,
                                           int b1, int slot, int t2) {
    char* xbuf = smem + SM_X0 + slot * XBUF;
    const float4* src = (const float4*)(Xea + (size_t)b1 * 19200);
#pragma unroll 1
    for (int base = 0; base < 4800; base += 1024) {
        float4 s[8];
#pragma unroll
        for (int i = 0; i < 8; ++i) {
            int f = base + t2 + 128 * i;
            if (f < 4800) s[i] = __ldg(src + f);
        }
#pragma unroll
        for (int i = 0; i < 8; ++i) {
            int f = base + t2 + 128 * i;
            if (f < 4800) {
                int idx = 4 * f;
                int r = idx / 150;
                int c = idx - 150 * r;
                __half2 p0 = __floats2half2_rn(s[i].x, s[i].y);
                __half2 p1 = __floats2half2_rn(s[i].z, s[i].w);
                *(__half2*)(xbuf + (r + 1) * XROWB + c * 2) = p0;
                int c2 = c + 2, r2 = r;
                if (c2 >= 150) { c2 -= 150; r2 += 1; }
                *(__half2*)(xbuf + (r2 + 1) * XROWB + c2 * 2) = p1;
            }
        }
    }
    // mask compaction
    int mk = Xmask[b1 * Ln + t2];
    unsigned bal = __ballot_sync(0xffffffffu, mk != 0);
    int* wc = (int*)(smem + SM_WC) + slot * 4;
    if ((t2 & 31) == 0) wc[t2 >> 5] = __popc(bal);
    asm volatile("bar.sync 2, 128;" ::: "memory");
    int c0 = wc[0], c1 = wc[1], c2 = wc[2], c3 = wc[3];
    int na = c0 + c1 + c2 + c3;
    uint8_t* act = (uint8_t*)(smem + SM_ACT) + slot * 128;
    uint8_t* pms = (uint8_t*)(smem + SM_PMS) + slot * 128;
    int wofs = (t2 >= 32 ? c0 : 0) + (t2 >= 64 ? c1 : 0) + (t2 >= 96 ? c2 : 0);
    if (mk != 0) {
        int r = wofs + __popc(bal & ((1u << (t2 & 31)) - 1u));
        act[r] = (uint8_t)t2;
        pms[r] = (uint8_t)mk;
    }
    if (t2 >= na) { act[t2] = 0; pms[t2] = 0; }
}

// ---------------- main: grid (2 h-halves, 74), 384 threads ----------------
__global__ __launch_bounds__(THREADS, 1)
void pcnn_mma_kernel(const float* __restrict__ Xea,
                     const int*   __restrict__ Xmask,
                     const float* __restrict__ bias,
                     float*       __restrict__ out)
{
    extern __shared__ char smem[];
    uint32_t sb;
    asm("{ .reg .u64 t; cvta.to.shared.u64 t, %1; cvt.u32.u64 %0, t; }"
        : "=r"(sb) : "l"(smem));
    const int t    = threadIdx.x;
    const int w    = t >> 5, lane = t & 31;
    const int hh   = blockIdx.x;
    const int y    = blockIdx.y;
    const int nj   = w & 3;       // n32 chunk (GEMM warps)
    const int mi   = (w >> 2) & 1; // m64 chunk

    if (t == 0) {
        asm volatile("mbarrier.init.shared.b64 [%0], 1;" :: "r"(sb + MB_W) : "memory");
    }
    __syncthreads();
    if (t == 0) {
        asm volatile("mbarrier.arrive.expect_tx.shared.b64 _, [%0], %1;"
                     :: "r"(sb + MB_W), "r"((uint32_t)WTILE) : "memory");
        asm volatile(
            "cp.async.bulk.shared::cluster.global.mbarrier::complete_tx::bytes "
            "[%0], [%1], %2, [%3];"
            :: "r"(sb + SM_W), "l"(Wg + (size_t)hh * 128 * WRS),
               "r"((uint32_t)WTILE), "r"(sb + MB_W) : "memory");
    }

    // zero both X buffers (halo rows + col padding stay zero forever)
    for (int i = t * 16; i < 2 * XBUF; i += THREADS * 16)
        *(uint4*)(smem + SM_X0 + i) = make_uint4(0, 0, 0, 0);
    __syncthreads();

    const int NB = (Bn - y + 73) / 74;

    // bootstrap: producers stage unit 0; GEMM warps wait for W
    if (w >= 8) {
        stage_unit(smem, Xea, Xmask, y, 0, t - 256);
    } else {
        mbar_wait(sb + MB_W, 0);
    }
    __syncthreads();

    // GEMM-warp invariants
    const uint32_t boff = sb + SM_W
        + (uint32_t)((nj * 32 + (lane & 7) + ((lane >> 4) << 3)) * WROWB)
        + (uint32_t)(((lane >> 3) & 1) * 16);
    const uint32_t colp = (uint32_t)((lane >> 4) << 4);
    float bb = 0.f;
    int   hok = 0;
    if (t < 128) {
        int h = hh * 128 + t;
        hok = (h < Hn);
        if (hok) bb = bias[h];
    }

    for (int u = 0; u < NB; ++u) {
        const int buf = u & 1;
        const int b   = y + 74 * u;

        if (w < 8) {
            // ---- consumer: GEMM over compacted rows ----
            const int* wc = (const int*)(smem + SM_WC) + buf * 4;
            const int na = wc[0] + wc[1] + wc[2] + wc[3];
            const uint8_t* act = (const uint8_t*)(smem + SM_ACT) + buf * 128;
            const uint8_t* pms = (const uint8_t*)(smem + SM_PMS) + buf * 128;

            float d[4][4][4];
#pragma unroll
            for (int i = 0; i < 4; ++i)
#pragma unroll
                for (int j = 0; j < 4; ++j)
#pragma unroll
                    for (int e = 0; e < 4; ++e) d[i][j][e] = 0.f;

            const uint32_t xb = sb + SM_X0 + buf * XBUF;
            uint32_t A[4];
#pragma unroll
            for (int mt = 0; mt < 4; ++mt)
                A[mt] = xb + (uint32_t)act[mi * 64 + mt * 16 + (lane & 15)] * XROWB + colp;

            int myrows = na - mi * 64;
            if (myrows > 64) myrows = 64;
            const int MT = (myrows <= 0) ? 0 : ((myrows + 15) >> 4);
            switch (MT) {
                case 4: gemm_run<4>(A, boff, d); break;
                case 3: gemm_run<3>(A, boff, d); break;
                case 2: gemm_run<2>(A, boff, d); break;
                case 1: gemm_run<1>(A, boff, d); break;
                default: break;
            }

            // ---- register epilogue: mask-gated max ----
            float pm[3][8];
#pragma unroll
            for (int m = 0; m < 3; ++m)
#pragma unroll
                for (int c = 0; c < 8; ++c) pm[m][c] = -INFINITY;

            const int rb = mi * 64 + (lane >> 2);
#pragma unroll
            for (int mt = 0; mt < 4; ++mt) {
                int mk0 = pms[rb + mt * 16];
                int mk1 = pms[rb + mt * 16 + 8];
#pragma unroll
                for (int j = 0; j < 4; ++j) {
                    float* v = d[mt][j];
                    if      (mk0 == 1) { pm[0][2*j] = fmaxf(pm[0][2*j], v[0]); pm[0][2*j+1] = fmaxf(pm[0][2*j+1], v[1]); }
                    else if (mk0 == 2) { pm[1][2*j] = fmaxf(pm[1][2*j], v[0]); pm[1][2*j+1] = fmaxf(pm[1][2*j+1], v[1]); }
                    else if (mk0 == 3) { pm[2][2*j] = fmaxf(pm[2][2*j], v[0]); pm[2][2*j+1] = fmaxf(pm[2][2*j+1], v[1]); }
                    if      (mk1 == 1) { pm[0][2*j] = fmaxf(pm[0][2*j], v[2]); pm[0][2*j+1] = fmaxf(pm[0][2*j+1], v[3]); }
                    else if (mk1 == 2) { pm[1][2*j] = fmaxf(pm[1][2*j], v[2]); pm[1][2*j+1] = fmaxf(pm[1][2*j+1], v[3]); }
                    else if (mk1 == 3) { pm[2][2*j] = fmaxf(pm[2][2*j], v[2]); pm[2][2*j+1] = fmaxf(pm[2][2*j+1], v[3]); }
                }
            }
#pragma unroll
            for (int off = 4; off <= 16; off <<= 1)
#pragma unroll
                for (int m = 0; m < 3; ++m)
#pragma unroll
                    for (int c = 0; c < 8; ++c)
                        pm[m][c] = fmaxf(pm[m][c],
                                         __shfl_xor_sync(0xffffffffu, pm[m][c], off));
            float* red = (float*)(smem + SM_RED);
            if (lane < 4) {
#pragma unroll
                for (int c = 0; c < 8; ++c) {
                    int col = nj * 32 + (c >> 1) * 8 + lane * 2 + (c & 1);
#pragma unroll
                    for (int m = 0; m < 3; ++m)
                        red[(mi * 128 + col) * 3 + m] = pm[m][c];
                }
            }
            asm volatile("bar.sync 1, 256;" ::: "memory");

            if (t < 128 && hok) {
                float* o = out + (size_t)b * (3 * Hn) + (hh * 128 + t) * 3;
#pragma unroll
                for (int m = 0; m < 3; ++m) {
                    float r = fmaxf(red[(0 * 128 + t) * 3 + m],
                                    red[(1 * 128 + t) * 3 + m]);
                    o[m] = tanhf(fmaxf(0.f, r + bb));
                }
            }
        } else {
            // ---- producer: stage next unit while GEMM runs ----
            if (u + 1 < NB)
                stage_unit(smem, Xea, Xmask, b + 74, buf ^ 1, t - 256);
        }
        __syncthreads();
    }
}

extern "C" void kernel_launch(void* const* d_in, const int* in_sizes, int n_in,
                              void* d_out, int out_size)
{
    const float* Xea   = (const float*)d_in[0];
    const int*   Xmask = (const int*)  d_in[1];
    const float* W     = (const float*)d_in[2];
    const float* bias  = (const float*)d_in[3];
    float*       out   = (float*)d_out;

    wprep<<<(2 * 128 * WRS + 255) / 256, 256>>>(W);

    cudaFuncSetAttribute(pcnn_mma_kernel,
                         cudaFuncAttributeMaxDynamicSharedMemorySize, SMEM_BYTES);
    dim3 grid(2, 74);
    pcnn_mma_kernel<<<grid, THREADS, SMEM_BYTES>>>(Xea, Xmask, bias, out);
}